// round 15
// baseline (speedup 1.0000x reference)
#include <cuda_runtime.h>
#include <cuda_fp16.h>
#include <cuda_bf16.h>
#include <cstdint>

#define N_NODES 20000
#define N_EDGES 640000
#define HID 256
#define KB2 512
#define D_OP 140
#define D_EMB 64
#define D_CFG 52
#define LN_EPS 1e-5f

// ---------------- scratch (device globals; no allocation) ----------------
// Ping-pong A matrices (fp16 hi/lo): cols 0-255 = x, 256-511 = agg
__device__ __half g_Ah0[N_NODES * KB2];
__device__ __half g_Al0[N_NODES * KB2];
__device__ __half g_Ah1[N_NODES * KB2];
__device__ __half g_Al1[N_NODES * KB2];
__device__ __half g_WBh[4 * HID * KB2];   // [layer][n=256][k=512] transposed concat W (fp16)
__device__ __half g_W1h[HID * HID];       // [n=256][k=256]
__device__ __half g_W2h[(HID / 2) * HID]; // [n=128][k=256]
__device__ int   g_deg[N_NODES];
__device__ float g_invdeg[N_NODES];
__device__ int   g_rowstart[N_NODES + 1];
__device__ int   g_cursor[N_NODES];
__device__ int   g_csr[N_EDGES];

__device__ __forceinline__ void f16split(float v, __half& h, __half& l) {
    h = __float2half_rn(v);
    l = __float2half_rn(v - __half2float(h));
}

// ---------------- graph preprocessing ----------------
__global__ void zero_kernel() {
    int i = blockIdx.x * blockDim.x + threadIdx.x;
    if (i < N_NODES) { g_deg[i] = 0; g_cursor[i] = 0; }
}

__global__ void deg_kernel(const int* __restrict__ dst) {
    int e = blockIdx.x * blockDim.x + threadIdx.x;
    if (e < N_EDGES) atomicAdd(&g_deg[dst[e]], 1);
}

__global__ void scan_kernel() {
    __shared__ int partial[256];
    int tid = threadIdx.x;
    const int CH = (N_NODES + 255) / 256;
    int base = tid * CH;
    int s = 0;
    for (int i = 0; i < CH; i++) {
        int idx = base + i;
        if (idx < N_NODES) s += g_deg[idx];
    }
    partial[tid] = s;
    __syncthreads();
    for (int off = 1; off < 256; off <<= 1) {
        int v = 0;
        if (tid >= off) v = partial[tid - off];
        __syncthreads();
        partial[tid] += v;
        __syncthreads();
    }
    int run = (tid == 0) ? 0 : partial[tid - 1];
    for (int i = 0; i < CH; i++) {
        int idx = base + i;
        if (idx < N_NODES) {
            int d = g_deg[idx];
            g_rowstart[idx] = run;
            run += d;
            g_invdeg[idx] = 1.0f / fmaxf((float)d, 1.0f);
        }
    }
    if (tid == 255) g_rowstart[N_NODES] = run;
}

__global__ void fill_kernel(const int* __restrict__ src, const int* __restrict__ dst) {
    int e = blockIdx.x * blockDim.x + threadIdx.x;
    if (e < N_EDGES) {
        int d = dst[e];
        int pos = atomicAdd(&g_cursor[d], 1);
        g_csr[g_rowstart[d] + pos] = src[e];
    }
}

// ---------------- weight transpose + fp16 round (once per launch) ----------------
#define W_LAYER (4 * HID * KB2)               // 524288
#define W_TOT (W_LAYER + HID * HID + (HID / 2) * HID)
__global__ void split_w_kernel(const float* __restrict__ Wself,
                               const float* __restrict__ Wneigh,
                               const float* __restrict__ W1,
                               const float* __restrict__ W2) {
    int i = blockIdx.x * blockDim.x + threadIdx.x;
    if (i >= W_TOT) return;
    float v; __half* dh; int di;
    if (i < W_LAYER) {
        int l = i >> 17;
        int rem = i & (HID * KB2 - 1);
        int n = rem >> 9, k = rem & 511;
        v = (k < HID) ? Wself[(l * HID + k) * HID + n]
                      : Wneigh[(l * HID + (k - HID)) * HID + n];
        dh = g_WBh; di = i;
    } else if (i < W_LAYER + HID * HID) {
        di = i - W_LAYER;
        int n = di >> 8, k = di & 255;
        v = W1[k * HID + n];
        dh = g_W1h;
    } else {
        di = i - (W_LAYER + HID * HID);
        int n = di >> 8, k = di & 255;
        v = W2[k * (HID / 2) + n];
        dh = g_W2h;
    }
    dh[di] = __float2half_rn(v);
}

// ---------------- input feature assembly (into buffer 0) ----------------
__global__ void build_x_kernel(const float* __restrict__ op_feats,
                               const float* __restrict__ cfg,
                               const float* __restrict__ emb,
                               const float* __restrict__ fmean,
                               const float* __restrict__ fstd,
                               const int* __restrict__ op_ids) {
    int n = blockIdx.x;
    int c = threadIdx.x;
    float v;
    if (c < D_OP)               v = op_feats[n * D_OP + c];
    else if (c < D_OP + D_EMB)  v = emb[op_ids[n] * D_EMB + (c - D_OP)];
    else                        v = cfg[n * D_CFG + (c - D_OP - D_EMB)];
    float xv = (v - fmean[c]) / fstd[c];
    f16split(xv, g_Ah0[n * KB2 + c], g_Al0[n * KB2 + c]);
}

// ---------------- fused: per-CTA agg prologue + fp16x2 GEMM + LayerNorm + ReLU ----------------
#define BM 64
#define AS 40   // halves per smem row (80B, LDSM conflict-free)

__device__ __forceinline__ void acc8(float* a, const uint4& r) {
    float2 p0 = __half22float2(*(const __half2*)&r.x);
    float2 p1 = __half22float2(*(const __half2*)&r.y);
    float2 p2 = __half22float2(*(const __half2*)&r.z);
    float2 p3 = __half22float2(*(const __half2*)&r.w);
    a[0] += p0.x; a[1] += p0.y; a[2] += p1.x; a[3] += p1.y;
    a[4] += p2.x; a[5] += p2.y; a[6] += p3.x; a[7] += p3.y;
}

__device__ __forceinline__ uint32_t sm_u32(const void* p) {
    uint32_t a;
    asm("{ .reg .u64 t; cvta.to.shared.u64 t, %1; cvt.u32.u64 %0, t; }" : "=r"(a) : "l"(p));
    return a;
}
__device__ __forceinline__ void cp16(uint32_t d, const void* s) {
    asm volatile("cp.async.cg.shared.global [%0], [%1], 16;" :: "r"(d), "l"(s));
}
__device__ __forceinline__ void cp16z(uint32_t d, const void* s, int sz) {
    asm volatile("cp.async.cg.shared.global [%0], [%1], 16, %2;" :: "r"(d), "l"(s), "r"(sz));
}
__device__ __forceinline__ void ldsm4(uint32_t* r, uint32_t addr) {
    asm volatile("ldmatrix.sync.aligned.m8n8.x4.shared.b16 {%0,%1,%2,%3}, [%4];"
        : "=r"(r[0]), "=r"(r[1]), "=r"(r[2]), "=r"(r[3]) : "r"(addr));
}
__device__ __forceinline__ void mma_f16(float* c, const uint32_t* a, const uint32_t* b) {
    asm volatile(
        "mma.sync.aligned.m16n8k16.row.col.f32.f16.f16.f32 "
        "{%0,%1,%2,%3}, {%4,%5,%6,%7}, {%8,%9}, {%0,%1,%2,%3};"
        : "+f"(c[0]), "+f"(c[1]), "+f"(c[2]), "+f"(c[3])
        : "r"(a[0]), "r"(a[1]), "r"(a[2]), "r"(a[3]), "r"(b[0]), "r"(b[1]));
}

template <int NC>
__global__ __launch_bounds__(256) void gemm_ln_kernel(
    __half* __restrict__ Agh, __half* __restrict__ Agl, int lda,   // read A; agg writes own rows' agg cols
    const __half* __restrict__ Bgh,
    const float* __restrict__ bias,
    const float* __restrict__ gamma, const float* __restrict__ beta,
    float* __restrict__ outF,           // stride NC (may be null)
    __half* __restrict__ outH,          // stride KB2 (may be null) — DIFFERENT buffer than Agh
    __half* __restrict__ outL,
    int K, int doAgg)
{
    constexpr int NT = NC / 32;
    constexpr int ASH = 0;
    constexpr int ASL = BM * AS;              // 2560
    constexpr int BSH = 2 * BM * AS;          // 5120
    constexpr int STAGE = 2 * BM * AS + NC * AS;   // halves
    constexpr int NB = NC / 64;               // B chunks per thread

    extern __shared__ uint16_t smem[];
    __shared__ float sm_red[4][BM];
    uint32_t s_base = sm_u32(smem);

    int tid = threadIdx.x;
    int lane = tid & 31, wid = tid >> 5;
    int warp_m = wid & 1, warp_n = wid >> 1;  // 2m x 4n
    int g = lane >> 2, tig = lane & 3;
    int lt = lane >> 3, lr = lane & 7;

    int row0 = blockIdx.x * BM;

    // A copy map: 64 rows x 4 chunks = 256 chunks; 1 per thread (hi+lo)
    int am = tid >> 2, ak = (tid & 3) * 8;
    // B copy map: NC rows x 4 chunks; NB per thread (hi only)
    int bn_[NB], bk_[NB];
#pragma unroll
    for (int r = 0; r < NB; r++) {
        int c = tid + 256 * r;
        bn_[r] = c >> 2;
        bk_[r] = (c & 3) * 8;
    }

    const int NIT = K / 32;

    auto ISSUE = [&](int it, int buf) {
        int k0 = it * 32;
        uint32_t st = s_base + buf * (STAGE * 2);
        {
            int gm = row0 + am;
            int cgm = (gm < N_NODES) ? gm : (N_NODES - 1);
            int sz = (gm < N_NODES) ? 16 : 0;
            size_t off = (size_t)cgm * lda + k0 + ak;
            uint32_t so = (am * AS + ak) * 2;
            cp16z(st + ASH * 2 + so, Agh + off, sz);
            cp16z(st + ASL * 2 + so, Agl + off, sz);
        }
#pragma unroll
        for (int r = 0; r < NB; r++) {
            size_t off = (size_t)bn_[r] * K + k0 + bk_[r];
            uint32_t so = (bn_[r] * AS + bk_[r]) * 2;
            cp16(st + BSH * 2 + so, Bgh + off);
        }
        asm volatile("cp.async.commit_group;");
    };

    // stage 0 (k=0..31: x columns, independent of agg) — issue before agg phase
    ISSUE(0, 0);

    // ---------------- fused aggregation prologue (this CTA's 64 rows) ----------------
    // Reads x cols (stable this launch: epilogue writes to the OTHER buffer).
    // Writes agg cols of OWN rows only; consumed only by this CTA after fence+sync.
    if (doAgg) {
        const uint4* __restrict__ xv = (const uint4*)Agh;   // 64 uint4/row; x = first 32
        int t = tid & 31;
        int rgrp = tid >> 5;                   // 8 rows per pass
        for (int rr = 0; rr < BM / 8; rr++) {
            int n = row0 + rr * 8 + rgrp;
            if (n < N_NODES) {
                int s0 = g_rowstart[n], s1 = g_rowstart[n + 1];
                float a[8];
#pragma unroll
                for (int i = 0; i < 8; i++) a[i] = 0.f;
                int j = s0;
                for (; j + 4 <= s1; j += 4) {
                    int i0 = g_csr[j], i1 = g_csr[j + 1], i2 = g_csr[j + 2], i3 = g_csr[j + 3];
                    uint4 r0 = xv[i0 * 64 + t];
                    uint4 r1 = xv[i1 * 64 + t];
                    uint4 r2 = xv[i2 * 64 + t];
                    uint4 r3 = xv[i3 * 64 + t];
                    acc8(a, r0); acc8(a, r1); acc8(a, r2); acc8(a, r3);
                }
                for (; j < s1; j++) {
                    uint4 r = xv[g_csr[j] * 64 + t];
                    acc8(a, r);
                }
                float id = g_invdeg[n];
                __half hh[8], ll[8];
#pragma unroll
                for (int i = 0; i < 8; i++) f16split(a[i] * id, hh[i], ll[i]);
                *(uint4*)&Agh[(size_t)n * KB2 + HID + t * 8] = *(const uint4*)hh;
                *(uint4*)&Agl[(size_t)n * KB2 + HID + t * 8] = *(const uint4*)ll;
            }
        }
        __threadfence();
        __syncthreads();
    }

    float acc[2][NT][4];
#pragma unroll
    for (int mt = 0; mt < 2; mt++)
#pragma unroll
        for (int nt = 0; nt < NT; nt++)
#pragma unroll
            for (int i = 0; i < 4; i++) acc[mt][nt][i] = 0.f;

    auto COMPUTE = [&](int buf) {
        uint32_t st = s_base + buf * (STAGE * 2);
#pragma unroll
        for (int ks = 0; ks < 2; ks++) {
            int k0 = ks * 16;
            uint32_t ah[2][4], al[2][4], bh[NT][2];
#pragma unroll
            for (int mt = 0; mt < 2; mt++) {
                int row = warp_m * 32 + mt * 16 + (lt & 1) * 8 + lr;
                int col = k0 + (lt >> 1) * 8;
                uint32_t off = (uint32_t)(row * AS + col) * 2;
                ldsm4(ah[mt], st + ASH * 2 + off);
                ldsm4(al[mt], st + ASL * 2 + off);
            }
#pragma unroll
            for (int p = 0; p < NT / 2; p++) {
                int nr = warp_n * (NC / 4) + p * 16 + (lt >> 1) * 8 + lr;
                int col = k0 + (lt & 1) * 8;
                uint32_t off = (uint32_t)(nr * AS + col) * 2;
                uint32_t t[4];
                ldsm4(t, st + BSH * 2 + off);
                bh[2 * p][0] = t[0]; bh[2 * p][1] = t[1];
                bh[2 * p + 1][0] = t[2]; bh[2 * p + 1][1] = t[3];
            }
#pragma unroll
            for (int mt = 0; mt < 2; mt++)
#pragma unroll
                for (int nt = 0; nt < NT; nt++) {
                    mma_f16(acc[mt][nt], ah[mt], bh[nt]);
                    mma_f16(acc[mt][nt], al[mt], bh[nt]);
                }
        }
    };

    int buf = 0;
    for (int it = 0; it < NIT; it++) {
        if (it + 1 < NIT) {
            ISSUE(it + 1, buf ^ 1);
            asm volatile("cp.async.wait_group 1;");
        } else {
            asm volatile("cp.async.wait_group 0;");
        }
        __syncthreads();
        COMPUTE(buf);
        __syncthreads();
        buf ^= 1;
    }

    // ---------------- fused epilogue: bias + LayerNorm + ReLU + writes ----------------
#pragma unroll
    for (int nt = 0; nt < NT; nt++) {
        int gc = warp_n * (NC / 4) + nt * 8 + 2 * tig;
        float b0 = bias ? bias[gc] : 0.f;
        float b1 = bias ? bias[gc + 1] : 0.f;
#pragma unroll
        for (int mt = 0; mt < 2; mt++) {
            acc[mt][nt][0] += b0; acc[mt][nt][1] += b1;
            acc[mt][nt][2] += b0; acc[mt][nt][3] += b1;
        }
    }

    // pass 1: row sums -> mean
    float mu[2][2];
#pragma unroll
    for (int mt = 0; mt < 2; mt++) {
        float s0 = 0.f, s1 = 0.f;
#pragma unroll
        for (int nt = 0; nt < NT; nt++) {
            s0 += acc[mt][nt][0] + acc[mt][nt][1];
            s1 += acc[mt][nt][2] + acc[mt][nt][3];
        }
        s0 += __shfl_xor_sync(0xFFFFFFFFu, s0, 1);
        s0 += __shfl_xor_sync(0xFFFFFFFFu, s0, 2);
        s1 += __shfl_xor_sync(0xFFFFFFFFu, s1, 1);
        s1 += __shfl_xor_sync(0xFFFFFFFFu, s1, 2);
        if (tig == 0) {
            int lr0 = warp_m * 32 + mt * 16 + g;
            sm_red[warp_n][lr0] = s0;
            sm_red[warp_n][lr0 + 8] = s1;
        }
    }
    __syncthreads();
#pragma unroll
    for (int mt = 0; mt < 2; mt++) {
        int lr0 = warp_m * 32 + mt * 16 + g;
        mu[mt][0] = (sm_red[0][lr0] + sm_red[1][lr0] + sm_red[2][lr0] + sm_red[3][lr0]) / (float)NC;
        mu[mt][1] = (sm_red[0][lr0 + 8] + sm_red[1][lr0 + 8] + sm_red[2][lr0 + 8] + sm_red[3][lr0 + 8]) / (float)NC;
    }
    __syncthreads();

    // pass 2: variance of deviations
    float rstd[2][2];
#pragma unroll
    for (int mt = 0; mt < 2; mt++) {
        float s0 = 0.f, s1 = 0.f;
#pragma unroll
        for (int nt = 0; nt < NT; nt++) {
            float d0 = acc[mt][nt][0] - mu[mt][0];
            float d1 = acc[mt][nt][1] - mu[mt][0];
            float d2 = acc[mt][nt][2] - mu[mt][1];
            float d3 = acc[mt][nt][3] - mu[mt][1];
            s0 += d0 * d0 + d1 * d1;
            s1 += d2 * d2 + d3 * d3;
        }
        s0 += __shfl_xor_sync(0xFFFFFFFFu, s0, 1);
        s0 += __shfl_xor_sync(0xFFFFFFFFu, s0, 2);
        s1 += __shfl_xor_sync(0xFFFFFFFFu, s1, 1);
        s1 += __shfl_xor_sync(0xFFFFFFFFu, s1, 2);
        if (tig == 0) {
            int lr0 = warp_m * 32 + mt * 16 + g;
            sm_red[warp_n][lr0] = s0;
            sm_red[warp_n][lr0 + 8] = s1;
        }
    }
    __syncthreads();
#pragma unroll
    for (int mt = 0; mt < 2; mt++) {
        int lr0 = warp_m * 32 + mt * 16 + g;
        float v0 = (sm_red[0][lr0] + sm_red[1][lr0] + sm_red[2][lr0] + sm_red[3][lr0]) / (float)NC;
        float v1 = (sm_red[0][lr0 + 8] + sm_red[1][lr0 + 8] + sm_red[2][lr0 + 8] + sm_red[3][lr0 + 8]) / (float)NC;
        rstd[mt][0] = rsqrtf(v0 + LN_EPS);
        rstd[mt][1] = rsqrtf(v1 + LN_EPS);
    }

    // normalize + relu + write
#pragma unroll
    for (int nt = 0; nt < NT; nt++) {
        int gc = warp_n * (NC / 4) + nt * 8 + 2 * tig;
        float ga0 = gamma[gc], ga1 = gamma[gc + 1];
        float be0 = beta[gc], be1 = beta[gc + 1];
#pragma unroll
        for (int mt = 0; mt < 2; mt++) {
#pragma unroll
            for (int h = 0; h < 2; h++) {
                int gr = row0 + warp_m * 32 + mt * 16 + g + h * 8;
                if (gr >= N_NODES) continue;
                float y0 = fmaxf((acc[mt][nt][2 * h] - mu[mt][h]) * rstd[mt][h] * ga0 + be0, 0.f);
                float y1 = fmaxf((acc[mt][nt][2 * h + 1] - mu[mt][h]) * rstd[mt][h] * ga1 + be1, 0.f);
                if (outF) *(float2*)&outF[(size_t)gr * NC + gc] = make_float2(y0, y1);
                if (outH) {
                    __half h0, l0, h1, l1;
                    f16split(y0, h0, l0);
                    f16split(y1, h1, l1);
                    __half2 hp2; hp2.x = h0; hp2.y = h1;
                    __half2 lp2; lp2.x = l0; lp2.y = l1;
                    *(__half2*)&outH[(size_t)gr * KB2 + gc] = hp2;
                    *(__half2*)&outL[(size_t)gr * KB2 + gc] = lp2;
                }
            }
        }
    }
}

// ---------------- launch ----------------
extern "C" void kernel_launch(void* const* d_in, const int* in_sizes, int n_in,
                              void* d_out, int out_size) {
    const float* op_feats    = (const float*)d_in[0];
    const float* config_f    = (const float*)d_in[1];
    const float* embed_table = (const float*)d_in[2];
    const float* feat_mean   = (const float*)d_in[3];
    const float* feat_std    = (const float*)d_in[4];
    const float* Wself       = (const float*)d_in[5];
    const float* Wneigh      = (const float*)d_in[6];
    const float* bconv       = (const float*)d_in[7];
    const float* conv_gamma  = (const float*)d_in[8];
    const float* conv_beta   = (const float*)d_in[9];
    const float* W1          = (const float*)d_in[10];
    const float* g1          = (const float*)d_in[11];
    const float* b1          = (const float*)d_in[12];
    const float* W2          = (const float*)d_in[13];
    const float* g2          = (const float*)d_in[14];
    const float* b2          = (const float*)d_in[15];
    const int*   op_ids      = (const int*)d_in[16];
    const int*   src         = (const int*)d_in[17];
    const int*   dst         = (const int*)d_in[18];
    float* out = (float*)d_out;

    __half *Ah[2], *Al[2], *WBh, *W1h, *W2h;
    cudaGetSymbolAddress((void**)&Ah[0], g_Ah0);
    cudaGetSymbolAddress((void**)&Al[0], g_Al0);
    cudaGetSymbolAddress((void**)&Ah[1], g_Ah1);
    cudaGetSymbolAddress((void**)&Al[1], g_Al1);
    cudaGetSymbolAddress((void**)&WBh, g_WBh);
    cudaGetSymbolAddress((void**)&W1h, g_W1h);
    cudaGetSymbolAddress((void**)&W2h, g_W2h);

    const int SMEM256 = 2 * (2 * BM * AS + 256 * AS) * 2;   // 61440 B
    const int SMEM128 = 2 * (2 * BM * AS + 128 * AS) * 2;   // 40960 B
    cudaFuncSetAttribute(gemm_ln_kernel<256>,
                         cudaFuncAttributeMaxDynamicSharedMemorySize, SMEM256);
    cudaFuncSetAttribute(gemm_ln_kernel<128>,
                         cudaFuncAttributeMaxDynamicSharedMemorySize, SMEM128);

    zero_kernel<<<(N_NODES + 255) / 256, 256>>>();
    deg_kernel<<<(N_EDGES + 255) / 256, 256>>>(dst);
    scan_kernel<<<1, 256>>>();
    fill_kernel<<<(N_EDGES + 255) / 256, 256>>>(src, dst);
    split_w_kernel<<<(W_TOT + 255) / 256, 256>>>(Wself, Wneigh, W1, W2);

    build_x_kernel<<<N_NODES, HID>>>(op_feats, config_f, embed_table,
                                     feat_mean, feat_std, op_ids);

    int nblk = (N_NODES + BM - 1) / BM;            // 313

    int p = 0;
    for (int i = 0; i < 4; i++) {
        gemm_ln_kernel<256><<<nblk, 256, SMEM256>>>(
            Ah[p], Al[p], KB2, WBh + i * HID * KB2,
            bconv + i * HID, conv_gamma + i * HID, conv_beta + i * HID,
            nullptr, Ah[p ^ 1], Al[p ^ 1], KB2, 1);
        p ^= 1;
    }

    gemm_ln_kernel<256><<<nblk, 256, SMEM256>>>(
        Ah[p], Al[p], KB2, W1h, nullptr, g1, b1,
        nullptr, Ah[p ^ 1], Al[p ^ 1], HID, 0);
    p ^= 1;

    gemm_ln_kernel<128><<<nblk, 256, SMEM128>>>(
        Ah[p], Al[p], KB2, W2h, nullptr, g2, b2,
        out, nullptr, nullptr, HID, 0);
}

// round 16
// speedup vs baseline: 1.3363x; 1.3363x over previous
#include <cuda_runtime.h>
#include <cuda_fp16.h>
#include <cuda_bf16.h>
#include <cstdint>

#define N_NODES 20000
#define N_EDGES 640000
#define HID 256
#define KB2 512
#define D_OP 140
#define D_EMB 64
#define D_CFG 52
#define LN_EPS 1e-5f

// ---------------- scratch (device globals; no allocation) ----------------
// A matrix fp16 hi/lo: cols 0-255 = x, 256-511 = agg. Agg gathers read hi cols 0-255.
__device__ __half g_Abh[N_NODES * KB2];
__device__ __half g_Abl[N_NODES * KB2];
__device__ __half g_WBh[4 * HID * KB2];   // [layer][n=256][k=512] transposed concat W (fp16)
__device__ __half g_W1h[HID * HID];       // [n=256][k=256]
__device__ __half g_W2h[(HID / 2) * HID]; // [n=128][k=256]
__device__ int   g_deg[N_NODES];
__device__ float g_invdeg[N_NODES];
__device__ int   g_rowstart[N_NODES + 1];
__device__ int   g_cursor[N_NODES];
__device__ int   g_csr[N_EDGES];

__device__ __forceinline__ void f16split(float v, __half& h, __half& l) {
    h = __float2half_rn(v);
    l = __float2half_rn(v - __half2float(h));
}

// ---------------- graph preprocessing ----------------
__global__ void zero_kernel() {
    int i = blockIdx.x * blockDim.x + threadIdx.x;
    if (i < N_NODES) { g_deg[i] = 0; g_cursor[i] = 0; }
}

__global__ void deg_kernel(const int* __restrict__ dst) {
    int e = blockIdx.x * blockDim.x + threadIdx.x;
    if (e < N_EDGES) atomicAdd(&g_deg[dst[e]], 1);
}

__global__ void scan_kernel() {
    __shared__ int partial[256];
    int tid = threadIdx.x;
    const int CH = (N_NODES + 255) / 256;
    int base = tid * CH;
    int s = 0;
    for (int i = 0; i < CH; i++) {
        int idx = base + i;
        if (idx < N_NODES) s += g_deg[idx];
    }
    partial[tid] = s;
    __syncthreads();
    for (int off = 1; off < 256; off <<= 1) {
        int v = 0;
        if (tid >= off) v = partial[tid - off];
        __syncthreads();
        partial[tid] += v;
        __syncthreads();
    }
    int run = (tid == 0) ? 0 : partial[tid - 1];
    for (int i = 0; i < CH; i++) {
        int idx = base + i;
        if (idx < N_NODES) {
            int d = g_deg[idx];
            g_rowstart[idx] = run;
            run += d;
            g_invdeg[idx] = 1.0f / fmaxf((float)d, 1.0f);
        }
    }
    if (tid == 255) g_rowstart[N_NODES] = run;
}

__global__ void fill_kernel(const int* __restrict__ src, const int* __restrict__ dst) {
    int e = blockIdx.x * blockDim.x + threadIdx.x;
    if (e < N_EDGES) {
        int d = dst[e];
        int pos = atomicAdd(&g_cursor[d], 1);
        g_csr[g_rowstart[d] + pos] = src[e];
    }
}

// ---------------- weight transpose + fp16 round (once per launch) ----------------
#define W_LAYER (4 * HID * KB2)               // 524288
#define W_TOT (W_LAYER + HID * HID + (HID / 2) * HID)
__global__ void split_w_kernel(const float* __restrict__ Wself,
                               const float* __restrict__ Wneigh,
                               const float* __restrict__ W1,
                               const float* __restrict__ W2) {
    int i = blockIdx.x * blockDim.x + threadIdx.x;
    if (i >= W_TOT) return;
    float v; __half* dh; int di;
    if (i < W_LAYER) {
        int l = i >> 17;
        int rem = i & (HID * KB2 - 1);
        int n = rem >> 9, k = rem & 511;
        v = (k < HID) ? Wself[(l * HID + k) * HID + n]
                      : Wneigh[(l * HID + (k - HID)) * HID + n];
        dh = g_WBh; di = i;
    } else if (i < W_LAYER + HID * HID) {
        di = i - W_LAYER;
        int n = di >> 8, k = di & 255;
        v = W1[k * HID + n];
        dh = g_W1h;
    } else {
        di = i - (W_LAYER + HID * HID);
        int n = di >> 8, k = di & 255;
        v = W2[k * (HID / 2) + n];
        dh = g_W2h;
    }
    dh[di] = __float2half_rn(v);
}

// ---------------- input feature assembly ----------------
__global__ void build_x_kernel(const float* __restrict__ op_feats,
                               const float* __restrict__ cfg,
                               const float* __restrict__ emb,
                               const float* __restrict__ fmean,
                               const float* __restrict__ fstd,
                               const int* __restrict__ op_ids) {
    int n = blockIdx.x;
    int c = threadIdx.x;
    float v;
    if (c < D_OP)               v = op_feats[n * D_OP + c];
    else if (c < D_OP + D_EMB)  v = emb[op_ids[n] * D_EMB + (c - D_OP)];
    else                        v = cfg[n * D_CFG + (c - D_OP - D_EMB)];
    float xv = (v - fmean[c]) / fstd[c];
    f16split(xv, g_Abh[n * KB2 + c], g_Abl[n * KB2 + c]);
}

// ---------------- neighbor mean aggregation: gather x-hi cols from A matrix ----------------
__device__ __forceinline__ void acc8(float* a, const uint4& r) {
    float2 p0 = __half22float2(*(const __half2*)&r.x);
    float2 p1 = __half22float2(*(const __half2*)&r.y);
    float2 p2 = __half22float2(*(const __half2*)&r.z);
    float2 p3 = __half22float2(*(const __half2*)&r.w);
    a[0] += p0.x; a[1] += p0.y; a[2] += p1.x; a[3] += p1.y;
    a[4] += p2.x; a[5] += p2.y; a[6] += p3.x; a[7] += p3.y;
}

__global__ __launch_bounds__(128) void agg_kernel() {
    int n = blockIdx.x * 4 + (threadIdx.x >> 5);
    if (n >= N_NODES) return;
    int t = threadIdx.x & 31;   // 32 threads/node, each owns 8 channels (uint4)
    int s0 = g_rowstart[n], s1 = g_rowstart[n + 1];
    const uint4* __restrict__ xv = (const uint4*)g_Abh;   // 64 uint4 per row; x = first 32

    float a[8];
#pragma unroll
    for (int i = 0; i < 8; i++) a[i] = 0.f;

    int j = s0;
    for (; j + 4 <= s1; j += 4) {
        int i0 = g_csr[j], i1 = g_csr[j + 1], i2 = g_csr[j + 2], i3 = g_csr[j + 3];
        uint4 r0 = xv[i0 * 64 + t];
        uint4 r1 = xv[i1 * 64 + t];
        uint4 r2 = xv[i2 * 64 + t];
        uint4 r3 = xv[i3 * 64 + t];
        acc8(a, r0); acc8(a, r1); acc8(a, r2); acc8(a, r3);
    }
    for (; j < s1; j++) {
        uint4 r = xv[g_csr[j] * 64 + t];
        acc8(a, r);
    }
    float id = g_invdeg[n];
    __half hh[8], ll[8];
#pragma unroll
    for (int i = 0; i < 8; i++) f16split(a[i] * id, hh[i], ll[i]);
    *(uint4*)&g_Abh[n * KB2 + HID + t * 8] = *(const uint4*)hh;
    *(uint4*)&g_Abl[n * KB2 + HID + t * 8] = *(const uint4*)ll;
}

// ---------------- fused fp16x2 GEMM + LayerNorm + ReLU (3-stage cp.async) ----------------
#define BM 64
#define AS 40   // halves per smem row (80B, LDSM conflict-free)

__device__ __forceinline__ uint32_t sm_u32(const void* p) {
    uint32_t a;
    asm("{ .reg .u64 t; cvta.to.shared.u64 t, %1; cvt.u32.u64 %0, t; }" : "=r"(a) : "l"(p));
    return a;
}
__device__ __forceinline__ void cp16(uint32_t d, const void* s) {
    asm volatile("cp.async.cg.shared.global [%0], [%1], 16;" :: "r"(d), "l"(s));
}
__device__ __forceinline__ void cp16z(uint32_t d, const void* s, int sz) {
    asm volatile("cp.async.cg.shared.global [%0], [%1], 16, %2;" :: "r"(d), "l"(s), "r"(sz));
}
__device__ __forceinline__ void ldsm4(uint32_t* r, uint32_t addr) {
    asm volatile("ldmatrix.sync.aligned.m8n8.x4.shared.b16 {%0,%1,%2,%3}, [%4];"
        : "=r"(r[0]), "=r"(r[1]), "=r"(r[2]), "=r"(r[3]) : "r"(addr));
}
__device__ __forceinline__ void mma_f16(float* c, const uint32_t* a, const uint32_t* b) {
    asm volatile(
        "mma.sync.aligned.m16n8k16.row.col.f32.f16.f16.f32 "
        "{%0,%1,%2,%3}, {%4,%5,%6,%7}, {%8,%9}, {%0,%1,%2,%3};"
        : "+f"(c[0]), "+f"(c[1]), "+f"(c[2]), "+f"(c[3])
        : "r"(a[0]), "r"(a[1]), "r"(a[2]), "r"(a[3]), "r"(b[0]), "r"(b[1]));
}

template <int NC>
__global__ __launch_bounds__(256) void gemm_ln_kernel(
    const __half* __restrict__ Agh, const __half* __restrict__ Agl, int lda,
    const __half* __restrict__ Bgh,
    const float* __restrict__ bias,
    const float* __restrict__ gamma, const float* __restrict__ beta,
    float* __restrict__ outF,           // stride NC (may be null)
    __half* __restrict__ outH,          // stride KB2 (may be null)
    __half* __restrict__ outL,
    int K)
{
    constexpr int NT = NC / 32;
    constexpr int ASH = 0;
    constexpr int ASL = BM * AS;              // 2560
    constexpr int BSH = 2 * BM * AS;          // 5120
    constexpr int STAGE = 2 * BM * AS + NC * AS;   // halves
    constexpr int NB = NC / 64;               // B chunks per thread

    extern __shared__ uint16_t smem[];
    __shared__ float sm_red[4][BM];
    uint32_t s_base = sm_u32(smem);

    int tid = threadIdx.x;
    int lane = tid & 31, wid = tid >> 5;
    int warp_m = wid & 1, warp_n = wid >> 1;  // 2m x 4n
    int g = lane >> 2, tig = lane & 3;
    int lt = lane >> 3, lr = lane & 7;

    int row0 = blockIdx.x * BM;

    // A copy map: 64 rows x 4 chunks = 256 chunks; 1 per thread (hi+lo)
    int am = tid >> 2, ak = (tid & 3) * 8;
    // B copy map: NC rows x 4 chunks; NB per thread (hi only)
    int bn_[NB], bk_[NB];
#pragma unroll
    for (int r = 0; r < NB; r++) {
        int c = tid + 256 * r;
        bn_[r] = c >> 2;
        bk_[r] = (c & 3) * 8;
    }

    float acc[2][NT][4];
#pragma unroll
    for (int mt = 0; mt < 2; mt++)
#pragma unroll
        for (int nt = 0; nt < NT; nt++)
#pragma unroll
            for (int i = 0; i < 4; i++) acc[mt][nt][i] = 0.f;

    const int NIT = K / 32;

    auto ISSUE = [&](int it, int stg) {
        int k0 = it * 32;
        uint32_t st = s_base + stg * (STAGE * 2);
        {
            int gm = row0 + am;
            int cgm = (gm < N_NODES) ? gm : (N_NODES - 1);
            int sz = (gm < N_NODES) ? 16 : 0;
            size_t off = (size_t)cgm * lda + k0 + ak;
            uint32_t so = (am * AS + ak) * 2;
            cp16z(st + ASH * 2 + so, Agh + off, sz);
            cp16z(st + ASL * 2 + so, Agl + off, sz);
        }
#pragma unroll
        for (int r = 0; r < NB; r++) {
            size_t off = (size_t)bn_[r] * K + k0 + bk_[r];
            uint32_t so = (bn_[r] * AS + bk_[r]) * 2;
            cp16(st + BSH * 2 + so, Bgh + off);
        }
        asm volatile("cp.async.commit_group;");
    };

    auto COMPUTE = [&](int stg) {
        uint32_t st = s_base + stg * (STAGE * 2);
#pragma unroll
        for (int ks = 0; ks < 2; ks++) {
            int k0 = ks * 16;
            uint32_t ah[2][4], al[2][4], bh[NT][2];
#pragma unroll
            for (int mt = 0; mt < 2; mt++) {
                int row = warp_m * 32 + mt * 16 + (lt & 1) * 8 + lr;
                int col = k0 + (lt >> 1) * 8;
                uint32_t off = (uint32_t)(row * AS + col) * 2;
                ldsm4(ah[mt], st + ASH * 2 + off);
                ldsm4(al[mt], st + ASL * 2 + off);
            }
#pragma unroll
            for (int p = 0; p < NT / 2; p++) {
                int nr = warp_n * (NC / 4) + p * 16 + (lt >> 1) * 8 + lr;
                int col = k0 + (lt & 1) * 8;
                uint32_t off = (uint32_t)(nr * AS + col) * 2;
                uint32_t t[4];
                ldsm4(t, st + BSH * 2 + off);
                bh[2 * p][0] = t[0]; bh[2 * p][1] = t[1];
                bh[2 * p + 1][0] = t[2]; bh[2 * p + 1][1] = t[3];
            }
#pragma unroll
            for (int mt = 0; mt < 2; mt++)
#pragma unroll
                for (int nt = 0; nt < NT; nt++) {
                    mma_f16(acc[mt][nt], ah[mt], bh[nt]);
                    mma_f16(acc[mt][nt], al[mt], bh[nt]);
                }
        }
    };

    // 3-stage pipeline, ONE sync per iteration.
    ISSUE(0, 0);
    if (NIT > 1) ISSUE(1, 1);
    for (int it = 0; it < NIT; it++) {
        if (it + 1 < NIT) {
            asm volatile("cp.async.wait_group 1;");
        } else {
            asm volatile("cp.async.wait_group 0;");
        }
        __syncthreads();   // all warps see stage it; all warps done with stage (it-1)%3
        if (it + 2 < NIT) ISSUE(it + 2, (it + 2) % 3);   // overwrites stage (it-1)%3: safe
        COMPUTE(it % 3);
    }

    // ---------------- fused epilogue: bias + LayerNorm + ReLU + writes ----------------
    __syncthreads();   // protect sm_red reuse vs last COMPUTE
#pragma unroll
    for (int nt = 0; nt < NT; nt++) {
        int gc = warp_n * (NC / 4) + nt * 8 + 2 * tig;
        float b0 = bias ? bias[gc] : 0.f;
        float b1 = bias ? bias[gc + 1] : 0.f;
#pragma unroll
        for (int mt = 0; mt < 2; mt++) {
            acc[mt][nt][0] += b0; acc[mt][nt][1] += b1;
            acc[mt][nt][2] += b0; acc[mt][nt][3] += b1;
        }
    }

    // pass 1: row sums -> mean
    float mu[2][2];
#pragma unroll
    for (int mt = 0; mt < 2; mt++) {
        float s0 = 0.f, s1 = 0.f;
#pragma unroll
        for (int nt = 0; nt < NT; nt++) {
            s0 += acc[mt][nt][0] + acc[mt][nt][1];
            s1 += acc[mt][nt][2] + acc[mt][nt][3];
        }
        s0 += __shfl_xor_sync(0xFFFFFFFFu, s0, 1);
        s0 += __shfl_xor_sync(0xFFFFFFFFu, s0, 2);
        s1 += __shfl_xor_sync(0xFFFFFFFFu, s1, 1);
        s1 += __shfl_xor_sync(0xFFFFFFFFu, s1, 2);
        if (tig == 0) {
            int lr0 = warp_m * 32 + mt * 16 + g;
            sm_red[warp_n][lr0] = s0;
            sm_red[warp_n][lr0 + 8] = s1;
        }
    }
    __syncthreads();
#pragma unroll
    for (int mt = 0; mt < 2; mt++) {
        int lr0 = warp_m * 32 + mt * 16 + g;
        mu[mt][0] = (sm_red[0][lr0] + sm_red[1][lr0] + sm_red[2][lr0] + sm_red[3][lr0]) / (float)NC;
        mu[mt][1] = (sm_red[0][lr0 + 8] + sm_red[1][lr0 + 8] + sm_red[2][lr0 + 8] + sm_red[3][lr0 + 8]) / (float)NC;
    }
    __syncthreads();

    // pass 2: variance of deviations
    float rstd[2][2];
#pragma unroll
    for (int mt = 0; mt < 2; mt++) {
        float s0 = 0.f, s1 = 0.f;
#pragma unroll
        for (int nt = 0; nt < NT; nt++) {
            float d0 = acc[mt][nt][0] - mu[mt][0];
            float d1 = acc[mt][nt][1] - mu[mt][0];
            float d2 = acc[mt][nt][2] - mu[mt][1];
            float d3 = acc[mt][nt][3] - mu[mt][1];
            s0 += d0 * d0 + d1 * d1;
            s1 += d2 * d2 + d3 * d3;
        }
        s0 += __shfl_xor_sync(0xFFFFFFFFu, s0, 1);
        s0 += __shfl_xor_sync(0xFFFFFFFFu, s0, 2);
        s1 += __shfl_xor_sync(0xFFFFFFFFu, s1, 1);
        s1 += __shfl_xor_sync(0xFFFFFFFFu, s1, 2);
        if (tig == 0) {
            int lr0 = warp_m * 32 + mt * 16 + g;
            sm_red[warp_n][lr0] = s0;
            sm_red[warp_n][lr0 + 8] = s1;
        }
    }
    __syncthreads();
#pragma unroll
    for (int mt = 0; mt < 2; mt++) {
        int lr0 = warp_m * 32 + mt * 16 + g;
        float v0 = (sm_red[0][lr0] + sm_red[1][lr0] + sm_red[2][lr0] + sm_red[3][lr0]) / (float)NC;
        float v1 = (sm_red[0][lr0 + 8] + sm_red[1][lr0 + 8] + sm_red[2][lr0 + 8] + sm_red[3][lr0 + 8]) / (float)NC;
        rstd[mt][0] = rsqrtf(v0 + LN_EPS);
        rstd[mt][1] = rsqrtf(v1 + LN_EPS);
    }

    // normalize + relu + write
#pragma unroll
    for (int nt = 0; nt < NT; nt++) {
        int gc = warp_n * (NC / 4) + nt * 8 + 2 * tig;
        float ga0 = gamma[gc], ga1 = gamma[gc + 1];
        float be0 = beta[gc], be1 = beta[gc + 1];
#pragma unroll
        for (int mt = 0; mt < 2; mt++) {
#pragma unroll
            for (int h = 0; h < 2; h++) {
                int gr = row0 + warp_m * 32 + mt * 16 + g + h * 8;
                if (gr >= N_NODES) continue;
                float y0 = fmaxf((acc[mt][nt][2 * h] - mu[mt][h]) * rstd[mt][h] * ga0 + be0, 0.f);
                float y1 = fmaxf((acc[mt][nt][2 * h + 1] - mu[mt][h]) * rstd[mt][h] * ga1 + be1, 0.f);
                if (outF) *(float2*)&outF[(size_t)gr * NC + gc] = make_float2(y0, y1);
                if (outH) {
                    __half h0, l0, h1, l1;
                    f16split(y0, h0, l0);
                    f16split(y1, h1, l1);
                    __half2 hp2; hp2.x = h0; hp2.y = h1;
                    __half2 lp2; lp2.x = l0; lp2.y = l1;
                    *(__half2*)&outH[(size_t)gr * KB2 + gc] = hp2;
                    *(__half2*)&outL[(size_t)gr * KB2 + gc] = lp2;
                }
            }
        }
    }
}

// ---------------- launch ----------------
extern "C" void kernel_launch(void* const* d_in, const int* in_sizes, int n_in,
                              void* d_out, int out_size) {
    const float* op_feats    = (const float*)d_in[0];
    const float* config_f    = (const float*)d_in[1];
    const float* embed_table = (const float*)d_in[2];
    const float* feat_mean   = (const float*)d_in[3];
    const float* feat_std    = (const float*)d_in[4];
    const float* Wself       = (const float*)d_in[5];
    const float* Wneigh      = (const float*)d_in[6];
    const float* bconv       = (const float*)d_in[7];
    const float* conv_gamma  = (const float*)d_in[8];
    const float* conv_beta   = (const float*)d_in[9];
    const float* W1          = (const float*)d_in[10];
    const float* g1          = (const float*)d_in[11];
    const float* b1          = (const float*)d_in[12];
    const float* W2          = (const float*)d_in[13];
    const float* g2          = (const float*)d_in[14];
    const float* b2          = (const float*)d_in[15];
    const int*   op_ids      = (const int*)d_in[16];
    const int*   src         = (const int*)d_in[17];
    const int*   dst         = (const int*)d_in[18];
    float* out = (float*)d_out;

    __half *Abh, *Abl, *WBh, *W1h, *W2h;
    cudaGetSymbolAddress((void**)&Abh, g_Abh);
    cudaGetSymbolAddress((void**)&Abl, g_Abl);
    cudaGetSymbolAddress((void**)&WBh, g_WBh);
    cudaGetSymbolAddress((void**)&W1h, g_W1h);
    cudaGetSymbolAddress((void**)&W2h, g_W2h);

    const int SMEM256 = 3 * (2 * BM * AS + 256 * AS) * 2;   // 92160 B
    const int SMEM128 = 3 * (2 * BM * AS + 128 * AS) * 2;   // 61440 B
    cudaFuncSetAttribute(gemm_ln_kernel<256>,
                         cudaFuncAttributeMaxDynamicSharedMemorySize, SMEM256);
    cudaFuncSetAttribute(gemm_ln_kernel<128>,
                         cudaFuncAttributeMaxDynamicSharedMemorySize, SMEM128);

    zero_kernel<<<(N_NODES + 255) / 256, 256>>>();
    deg_kernel<<<(N_EDGES + 255) / 256, 256>>>(dst);
    scan_kernel<<<1, 256>>>();
    fill_kernel<<<(N_EDGES + 255) / 256, 256>>>(src, dst);
    split_w_kernel<<<(W_TOT + 255) / 256, 256>>>(Wself, Wneigh, W1, W2);

    build_x_kernel<<<N_NODES, HID>>>(op_feats, config_f, embed_table,
                                     feat_mean, feat_std, op_ids);

    int nblk = (N_NODES + BM - 1) / BM;            // 313
    int ablk = (N_NODES + 3) / 4;                  // 5000

    for (int i = 0; i < 4; i++) {
        agg_kernel<<<ablk, 128>>>();
        gemm_ln_kernel<256><<<nblk, 256, SMEM256>>>(
            Abh, Abl, KB2, WBh + i * HID * KB2,
            bconv + i * HID, conv_gamma + i * HID, conv_beta + i * HID,
            nullptr, Abh, Abl, KB2);
    }

    gemm_ln_kernel<256><<<nblk, 256, SMEM256>>>(
        Abh, Abl, KB2, W1h, nullptr, g1, b1,
        nullptr, Abh, Abl, HID);

    gemm_ln_kernel<128><<<nblk, 256, SMEM128>>>(
        Abh, Abl, KB2, W2h, nullptr, g2, b2,
        out, nullptr, nullptr, HID);
}

// round 17
// speedup vs baseline: 1.6563x; 1.2394x over previous
#include <cuda_runtime.h>
#include <cuda_fp16.h>
#include <cuda_bf16.h>
#include <cstdint>

#define N_NODES 20000
#define N_EDGES 640000
#define HID 256
#define KB2 512
#define D_OP 140
#define D_EMB 64
#define D_CFG 52
#define LN_EPS 1e-5f

// ---------------- scratch (device globals; no allocation) ----------------
// A matrix fp16: cols 0-255 = x, 256-511 = agg.
__device__ __half g_Ab[N_NODES * KB2];
__device__ __half g_WBh[4 * HID * KB2];   // [layer][n=256][k=512] transposed concat W (fp16)
__device__ __half g_W1h[HID * HID];       // [n=256][k=256]
__device__ __half g_W2h[(HID / 2) * HID]; // [n=128][k=256]
__device__ int   g_deg[N_NODES];
__device__ float g_invdeg[N_NODES];
__device__ int   g_rowstart[N_NODES + 1];
__device__ int   g_cursor[N_NODES];
__device__ int   g_csr[N_EDGES];

// ---------------- graph preprocessing ----------------
__global__ void zero_kernel() {
    int i = blockIdx.x * blockDim.x + threadIdx.x;
    if (i < N_NODES) { g_deg[i] = 0; g_cursor[i] = 0; }
}

__global__ void deg_kernel(const int* __restrict__ dst) {
    int e = blockIdx.x * blockDim.x + threadIdx.x;
    if (e < N_EDGES) atomicAdd(&g_deg[dst[e]], 1);
}

__global__ void scan_kernel() {
    __shared__ int partial[256];
    int tid = threadIdx.x;
    const int CH = (N_NODES + 255) / 256;
    int base = tid * CH;
    int s = 0;
    for (int i = 0; i < CH; i++) {
        int idx = base + i;
        if (idx < N_NODES) s += g_deg[idx];
    }
    partial[tid] = s;
    __syncthreads();
    for (int off = 1; off < 256; off <<= 1) {
        int v = 0;
        if (tid >= off) v = partial[tid - off];
        __syncthreads();
        partial[tid] += v;
        __syncthreads();
    }
    int run = (tid == 0) ? 0 : partial[tid - 1];
    for (int i = 0; i < CH; i++) {
        int idx = base + i;
        if (idx < N_NODES) {
            int d = g_deg[idx];
            g_rowstart[idx] = run;
            run += d;
            g_invdeg[idx] = 1.0f / fmaxf((float)d, 1.0f);
        }
    }
    if (tid == 255) g_rowstart[N_NODES] = run;
}

__global__ void fill_kernel(const int* __restrict__ src, const int* __restrict__ dst) {
    int e = blockIdx.x * blockDim.x + threadIdx.x;
    if (e < N_EDGES) {
        int d = dst[e];
        int pos = atomicAdd(&g_cursor[d], 1);
        g_csr[g_rowstart[d] + pos] = src[e];
    }
}

// ---------------- weight transpose + fp16 round (once per launch) ----------------
#define W_LAYER (4 * HID * KB2)               // 524288
#define W_TOT (W_LAYER + HID * HID + (HID / 2) * HID)
__global__ void split_w_kernel(const float* __restrict__ Wself,
                               const float* __restrict__ Wneigh,
                               const float* __restrict__ W1,
                               const float* __restrict__ W2) {
    int i = blockIdx.x * blockDim.x + threadIdx.x;
    if (i >= W_TOT) return;
    float v; __half* dh; int di;
    if (i < W_LAYER) {
        int l = i >> 17;
        int rem = i & (HID * KB2 - 1);
        int n = rem >> 9, k = rem & 511;
        v = (k < HID) ? Wself[(l * HID + k) * HID + n]
                      : Wneigh[(l * HID + (k - HID)) * HID + n];
        dh = g_WBh; di = i;
    } else if (i < W_LAYER + HID * HID) {
        di = i - W_LAYER;
        int n = di >> 8, k = di & 255;
        v = W1[k * HID + n];
        dh = g_W1h;
    } else {
        di = i - (W_LAYER + HID * HID);
        int n = di >> 8, k = di & 255;
        v = W2[k * (HID / 2) + n];
        dh = g_W2h;
    }
    dh[di] = __float2half_rn(v);
}

// ---------------- input feature assembly ----------------
__global__ void build_x_kernel(const float* __restrict__ op_feats,
                               const float* __restrict__ cfg,
                               const float* __restrict__ emb,
                               const float* __restrict__ fmean,
                               const float* __restrict__ fstd,
                               const int* __restrict__ op_ids) {
    int n = blockIdx.x;
    int c = threadIdx.x;
    float v;
    if (c < D_OP)               v = op_feats[n * D_OP + c];
    else if (c < D_OP + D_EMB)  v = emb[op_ids[n] * D_EMB + (c - D_OP)];
    else                        v = cfg[n * D_CFG + (c - D_OP - D_EMB)];
    float xv = (v - fmean[c]) / fstd[c];
    g_Ab[n * KB2 + c] = __float2half_rn(xv);
}

// ---------------- neighbor mean aggregation: gather x cols from A matrix ----------------
__device__ __forceinline__ void acc8(float* a, const uint4& r) {
    float2 p0 = __half22float2(*(const __half2*)&r.x);
    float2 p1 = __half22float2(*(const __half2*)&r.y);
    float2 p2 = __half22float2(*(const __half2*)&r.z);
    float2 p3 = __half22float2(*(const __half2*)&r.w);
    a[0] += p0.x; a[1] += p0.y; a[2] += p1.x; a[3] += p1.y;
    a[4] += p2.x; a[5] += p2.y; a[6] += p3.x; a[7] += p3.y;
}

__global__ __launch_bounds__(128) void agg_kernel() {
    int n = blockIdx.x * 4 + (threadIdx.x >> 5);
    if (n >= N_NODES) return;
    int t = threadIdx.x & 31;   // 32 threads/node, each owns 8 channels (uint4)
    int s0 = g_rowstart[n], s1 = g_rowstart[n + 1];
    const uint4* __restrict__ xv = (const uint4*)g_Ab;   // 64 uint4 per row; x = first 32

    float a[8];
#pragma unroll
    for (int i = 0; i < 8; i++) a[i] = 0.f;

    int j = s0;
    for (; j + 4 <= s1; j += 4) {
        int i0 = g_csr[j], i1 = g_csr[j + 1], i2 = g_csr[j + 2], i3 = g_csr[j + 3];
        uint4 r0 = xv[i0 * 64 + t];
        uint4 r1 = xv[i1 * 64 + t];
        uint4 r2 = xv[i2 * 64 + t];
        uint4 r3 = xv[i3 * 64 + t];
        acc8(a, r0); acc8(a, r1); acc8(a, r2); acc8(a, r3);
    }
    for (; j < s1; j++) {
        uint4 r = xv[g_csr[j] * 64 + t];
        acc8(a, r);
    }
    float id = g_invdeg[n];
    __half hh[8];
#pragma unroll
    for (int i = 0; i < 8; i++) hh[i] = __float2half_rn(a[i] * id);
    *(uint4*)&g_Ab[n * KB2 + HID + t * 8] = *(const uint4*)hh;
}

// ---------------- fused fp16 GEMM + LayerNorm + ReLU (2-stage cp.async) ----------------
#define BM 64
#define AS 40   // halves per smem row (80B, LDSM conflict-free)

__device__ __forceinline__ uint32_t sm_u32(const void* p) {
    uint32_t a;
    asm("{ .reg .u64 t; cvta.to.shared.u64 t, %1; cvt.u32.u64 %0, t; }" : "=r"(a) : "l"(p));
    return a;
}
__device__ __forceinline__ void cp16(uint32_t d, const void* s) {
    asm volatile("cp.async.cg.shared.global [%0], [%1], 16;" :: "r"(d), "l"(s));
}
__device__ __forceinline__ void cp16z(uint32_t d, const void* s, int sz) {
    asm volatile("cp.async.cg.shared.global [%0], [%1], 16, %2;" :: "r"(d), "l"(s), "r"(sz));
}
__device__ __forceinline__ void ldsm4(uint32_t* r, uint32_t addr) {
    asm volatile("ldmatrix.sync.aligned.m8n8.x4.shared.b16 {%0,%1,%2,%3}, [%4];"
        : "=r"(r[0]), "=r"(r[1]), "=r"(r[2]), "=r"(r[3]) : "r"(addr));
}
__device__ __forceinline__ void mma_f16(float* c, const uint32_t* a, const uint32_t* b) {
    asm volatile(
        "mma.sync.aligned.m16n8k16.row.col.f32.f16.f16.f32 "
        "{%0,%1,%2,%3}, {%4,%5,%6,%7}, {%8,%9}, {%0,%1,%2,%3};"
        : "+f"(c[0]), "+f"(c[1]), "+f"(c[2]), "+f"(c[3])
        : "r"(a[0]), "r"(a[1]), "r"(a[2]), "r"(a[3]), "r"(b[0]), "r"(b[1]));
}

template <int NC>
__global__ __launch_bounds__(256) void gemm_ln_kernel(
    const __half* __restrict__ Ag, int lda,
    const __half* __restrict__ Bgh,
    const float* __restrict__ bias,
    const float* __restrict__ gamma, const float* __restrict__ beta,
    float* __restrict__ outF,           // stride NC (may be null)
    __half* __restrict__ outH,          // stride KB2 (may be null)
    int K)
{
    constexpr int NT = NC / 32;
    constexpr int ASH = 0;
    constexpr int BSH = BM * AS;              // 2560
    constexpr int STAGE = BM * AS + NC * AS;  // halves
    constexpr int NB = NC / 64;               // B chunks per thread

    extern __shared__ uint16_t smem[];
    __shared__ float sm_red[4][BM];
    uint32_t s_base = sm_u32(smem);

    int tid = threadIdx.x;
    int lane = tid & 31, wid = tid >> 5;
    int warp_m = wid & 1, warp_n = wid >> 1;  // 2m x 4n
    int g = lane >> 2, tig = lane & 3;
    int lt = lane >> 3, lr = lane & 7;

    int row0 = blockIdx.x * BM;

    // A copy map: 64 rows x 4 chunks = 256 chunks; 1 per thread
    int am = tid >> 2, ak = (tid & 3) * 8;
    // B copy map: NC rows x 4 chunks; NB per thread
    int bn_[NB], bk_[NB];
#pragma unroll
    for (int r = 0; r < NB; r++) {
        int c = tid + 256 * r;
        bn_[r] = c >> 2;
        bk_[r] = (c & 3) * 8;
    }

    float acc[2][NT][4];
#pragma unroll
    for (int mt = 0; mt < 2; mt++)
#pragma unroll
        for (int nt = 0; nt < NT; nt++)
#pragma unroll
            for (int i = 0; i < 4; i++) acc[mt][nt][i] = 0.f;

    const int NIT = K / 32;

    auto ISSUE = [&](int it, int buf) {
        int k0 = it * 32;
        uint32_t st = s_base + buf * (STAGE * 2);
        {
            int gm = row0 + am;
            int cgm = (gm < N_NODES) ? gm : (N_NODES - 1);
            int sz = (gm < N_NODES) ? 16 : 0;
            size_t off = (size_t)cgm * lda + k0 + ak;
            uint32_t so = (am * AS + ak) * 2;
            cp16z(st + ASH * 2 + so, Ag + off, sz);
        }
#pragma unroll
        for (int r = 0; r < NB; r++) {
            size_t off = (size_t)bn_[r] * K + k0 + bk_[r];
            uint32_t so = (bn_[r] * AS + bk_[r]) * 2;
            cp16(st + BSH * 2 + so, Bgh + off);
        }
        asm volatile("cp.async.commit_group;");
    };

    auto COMPUTE = [&](int buf) {
        uint32_t st = s_base + buf * (STAGE * 2);
#pragma unroll
        for (int ks = 0; ks < 2; ks++) {
            int k0 = ks * 16;
            uint32_t ah[2][4], bh[NT][2];
#pragma unroll
            for (int mt = 0; mt < 2; mt++) {
                int row = warp_m * 32 + mt * 16 + (lt & 1) * 8 + lr;
                int col = k0 + (lt >> 1) * 8;
                uint32_t off = (uint32_t)(row * AS + col) * 2;
                ldsm4(ah[mt], st + ASH * 2 + off);
            }
#pragma unroll
            for (int p = 0; p < NT / 2; p++) {
                int nr = warp_n * (NC / 4) + p * 16 + (lt >> 1) * 8 + lr;
                int col = k0 + (lt & 1) * 8;
                uint32_t off = (uint32_t)(nr * AS + col) * 2;
                uint32_t t[4];
                ldsm4(t, st + BSH * 2 + off);
                bh[2 * p][0] = t[0]; bh[2 * p][1] = t[1];
                bh[2 * p + 1][0] = t[2]; bh[2 * p + 1][1] = t[3];
            }
#pragma unroll
            for (int mt = 0; mt < 2; mt++)
#pragma unroll
                for (int nt = 0; nt < NT; nt++)
                    mma_f16(acc[mt][nt], ah[mt], bh[nt]);
        }
    };

    ISSUE(0, 0);
    int buf = 0;
    for (int it = 0; it < NIT; it++) {
        if (it + 1 < NIT) {
            ISSUE(it + 1, buf ^ 1);
            asm volatile("cp.async.wait_group 1;");
        } else {
            asm volatile("cp.async.wait_group 0;");
        }
        __syncthreads();
        COMPUTE(buf);
        __syncthreads();
        buf ^= 1;
    }

    // ---------------- fused epilogue: bias + LayerNorm + ReLU + writes ----------------
#pragma unroll
    for (int nt = 0; nt < NT; nt++) {
        int gc = warp_n * (NC / 4) + nt * 8 + 2 * tig;
        float b0 = bias ? bias[gc] : 0.f;
        float b1 = bias ? bias[gc + 1] : 0.f;
#pragma unroll
        for (int mt = 0; mt < 2; mt++) {
            acc[mt][nt][0] += b0; acc[mt][nt][1] += b1;
            acc[mt][nt][2] += b0; acc[mt][nt][3] += b1;
        }
    }

    // pass 1: row sums -> mean
    float mu[2][2];
#pragma unroll
    for (int mt = 0; mt < 2; mt++) {
        float s0 = 0.f, s1 = 0.f;
#pragma unroll
        for (int nt = 0; nt < NT; nt++) {
            s0 += acc[mt][nt][0] + acc[mt][nt][1];
            s1 += acc[mt][nt][2] + acc[mt][nt][3];
        }
        s0 += __shfl_xor_sync(0xFFFFFFFFu, s0, 1);
        s0 += __shfl_xor_sync(0xFFFFFFFFu, s0, 2);
        s1 += __shfl_xor_sync(0xFFFFFFFFu, s1, 1);
        s1 += __shfl_xor_sync(0xFFFFFFFFu, s1, 2);
        if (tig == 0) {
            int lr0 = warp_m * 32 + mt * 16 + g;
            sm_red[warp_n][lr0] = s0;
            sm_red[warp_n][lr0 + 8] = s1;
        }
    }
    __syncthreads();
#pragma unroll
    for (int mt = 0; mt < 2; mt++) {
        int lr0 = warp_m * 32 + mt * 16 + g;
        mu[mt][0] = (sm_red[0][lr0] + sm_red[1][lr0] + sm_red[2][lr0] + sm_red[3][lr0]) / (float)NC;
        mu[mt][1] = (sm_red[0][lr0 + 8] + sm_red[1][lr0 + 8] + sm_red[2][lr0 + 8] + sm_red[3][lr0 + 8]) / (float)NC;
    }
    __syncthreads();

    // pass 2: variance of deviations
    float rstd[2][2];
#pragma unroll
    for (int mt = 0; mt < 2; mt++) {
        float s0 = 0.f, s1 = 0.f;
#pragma unroll
        for (int nt = 0; nt < NT; nt++) {
            float d0 = acc[mt][nt][0] - mu[mt][0];
            float d1 = acc[mt][nt][1] - mu[mt][0];
            float d2 = acc[mt][nt][2] - mu[mt][1];
            float d3 = acc[mt][nt][3] - mu[mt][1];
            s0 += d0 * d0 + d1 * d1;
            s1 += d2 * d2 + d3 * d3;
        }
        s0 += __shfl_xor_sync(0xFFFFFFFFu, s0, 1);
        s0 += __shfl_xor_sync(0xFFFFFFFFu, s0, 2);
        s1 += __shfl_xor_sync(0xFFFFFFFFu, s1, 1);
        s1 += __shfl_xor_sync(0xFFFFFFFFu, s1, 2);
        if (tig == 0) {
            int lr0 = warp_m * 32 + mt * 16 + g;
            sm_red[warp_n][lr0] = s0;
            sm_red[warp_n][lr0 + 8] = s1;
        }
    }
    __syncthreads();
#pragma unroll
    for (int mt = 0; mt < 2; mt++) {
        int lr0 = warp_m * 32 + mt * 16 + g;
        float v0 = (sm_red[0][lr0] + sm_red[1][lr0] + sm_red[2][lr0] + sm_red[3][lr0]) / (float)NC;
        float v1 = (sm_red[0][lr0 + 8] + sm_red[1][lr0 + 8] + sm_red[2][lr0 + 8] + sm_red[3][lr0 + 8]) / (float)NC;
        rstd[mt][0] = rsqrtf(v0 + LN_EPS);
        rstd[mt][1] = rsqrtf(v1 + LN_EPS);
    }

    // normalize + relu + write
#pragma unroll
    for (int nt = 0; nt < NT; nt++) {
        int gc = warp_n * (NC / 4) + nt * 8 + 2 * tig;
        float ga0 = gamma[gc], ga1 = gamma[gc + 1];
        float be0 = beta[gc], be1 = beta[gc + 1];
#pragma unroll
        for (int mt = 0; mt < 2; mt++) {
#pragma unroll
            for (int h = 0; h < 2; h++) {
                int gr = row0 + warp_m * 32 + mt * 16 + g + h * 8;
                if (gr >= N_NODES) continue;
                float y0 = fmaxf((acc[mt][nt][2 * h] - mu[mt][h]) * rstd[mt][h] * ga0 + be0, 0.f);
                float y1 = fmaxf((acc[mt][nt][2 * h + 1] - mu[mt][h]) * rstd[mt][h] * ga1 + be1, 0.f);
                if (outF) *(float2*)&outF[(size_t)gr * NC + gc] = make_float2(y0, y1);
                if (outH) {
                    __half2 hv = __floats2half2_rn(y0, y1);
                    *(__half2*)&outH[(size_t)gr * KB2 + gc] = hv;
                }
            }
        }
    }
}

// ---------------- launch ----------------
extern "C" void kernel_launch(void* const* d_in, const int* in_sizes, int n_in,
                              void* d_out, int out_size) {
    const float* op_feats    = (const float*)d_in[0];
    const float* config_f    = (const float*)d_in[1];
    const float* embed_table = (const float*)d_in[2];
    const float* feat_mean   = (const float*)d_in[3];
    const float* feat_std    = (const float*)d_in[4];
    const float* Wself       = (const float*)d_in[5];
    const float* Wneigh      = (const float*)d_in[6];
    const float* bconv       = (const float*)d_in[7];
    const float* conv_gamma  = (const float*)d_in[8];
    const float* conv_beta   = (const float*)d_in[9];
    const float* W1          = (const float*)d_in[10];
    const float* g1          = (const float*)d_in[11];
    const float* b1          = (const float*)d_in[12];
    const float* W2          = (const float*)d_in[13];
    const float* g2          = (const float*)d_in[14];
    const float* b2          = (const float*)d_in[15];
    const int*   op_ids      = (const int*)d_in[16];
    const int*   src         = (const int*)d_in[17];
    const int*   dst         = (const int*)d_in[18];
    float* out = (float*)d_out;

    __half *Ab, *WBh, *W1h, *W2h;
    cudaGetSymbolAddress((void**)&Ab, g_Ab);
    cudaGetSymbolAddress((void**)&WBh, g_WBh);
    cudaGetSymbolAddress((void**)&W1h, g_W1h);
    cudaGetSymbolAddress((void**)&W2h, g_W2h);

    const int SMEM256 = 2 * (BM * AS + 256 * AS) * 2;   // 51200 B
    const int SMEM128 = 2 * (BM * AS + 128 * AS) * 2;   // 30720 B
    cudaFuncSetAttribute(gemm_ln_kernel<256>,
                         cudaFuncAttributeMaxDynamicSharedMemorySize, SMEM256);
    cudaFuncSetAttribute(gemm_ln_kernel<128>,
                         cudaFuncAttributeMaxDynamicSharedMemorySize, SMEM128);

    zero_kernel<<<(N_NODES + 255) / 256, 256>>>();
    deg_kernel<<<(N_EDGES + 255) / 256, 256>>>(dst);
    scan_kernel<<<1, 256>>>();
    fill_kernel<<<(N_EDGES + 255) / 256, 256>>>(src, dst);
    split_w_kernel<<<(W_TOT + 255) / 256, 256>>>(Wself, Wneigh, W1, W2);

    build_x_kernel<<<N_NODES, HID>>>(op_feats, config_f, embed_table,
                                     feat_mean, feat_std, op_ids);

    int nblk = (N_NODES + BM - 1) / BM;            // 313
    int ablk = (N_NODES + 3) / 4;                  // 5000

    for (int i = 0; i < 4; i++) {
        agg_kernel<<<ablk, 128>>>();
        gemm_ln_kernel<256><<<nblk, 256, SMEM256>>>(
            Ab, KB2, WBh + i * HID * KB2,
            bconv + i * HID, conv_gamma + i * HID, conv_beta + i * HID,
            nullptr, Ab, KB2);
    }

    gemm_ln_kernel<256><<<nblk, 256, SMEM256>>>(
        Ab, KB2, W1h, nullptr, g1, b1,
        nullptr, Ab, HID);

    gemm_ln_kernel<128><<<nblk, 256, SMEM128>>>(
        Ab, KB2, W2h, nullptr, g2, b2,
        out, nullptr, HID);
}